// round 13
// baseline (speedup 1.0000x reference)
#include <cuda_runtime.h>
#include <stdint.h>
#include <math.h>

#define H      500
#define H3     1500
#define S      256
#define V      50257
#define VP     50272            // V padded (128B row alignment)
#define MAXL   64
#define SOS    1

// scan: 16 CTAs per direction = ONE 16-CTA cluster, 1024 threads, warp-per-unit
#define SC_CPD     16
#define SC_THREADS 1024
#define SC_UPC     32

#define DEC_CTAS     128
#define DEC_THREADS  256

// ---------------------------------------------------------------------------
// Device scratch
// ---------------------------------------------------------------------------
__device__ float g_gxf[S * H3];
__device__ float g_gxb[S * H3];
__device__ float g_x1[S * 2 * H];
__device__ float g_y1f[S * H];
__device__ float g_y1b[S * H];
__device__ float g_enc[S * H];
__device__ float g_P[S * H];
__device__ float g_PT[H * S];
__device__ float g_dh[2][2][512];      // [parity][layer][unit]
__device__ float g_scores[S];
__device__ float g_wc[512];
__device__ float g_c[512];
__device__ float g_oWT[(size_t)H * VP];
__device__ float g_logits[(size_t)MAXL * V];
__device__ unsigned long long g_slots[MAXL];
__device__ unsigned g_ctr[8];          // ctr[5]: scan epilogue

// ---------------------------------------------------------------------------
// Helpers
// ---------------------------------------------------------------------------
__device__ __forceinline__ float sigf(float x) { return 1.f / (1.f + expf(-x)); }

__device__ __forceinline__ float wred(float v) {
#pragma unroll
    for (int o = 16; o; o >>= 1) v += __shfl_xor_sync(0xffffffffu, v, o);
    return v;
}

__device__ __forceinline__ unsigned fflip(float f) {
    unsigned u = __float_as_uint(f);
    return (u & 0x80000000u) ? ~u : (u | 0x80000000u);
}
__device__ __forceinline__ float unflip(unsigned u) {
    return (u & 0x80000000u) ? __uint_as_float(u ^ 0x80000000u)
                             : __uint_as_float(~u);
}

__device__ __forceinline__ void stcg(float* p, float v) {
    asm volatile("st.global.cg.f32 [%0], %1;" :: "l"(p), "f"(v) : "memory");
}
__device__ __forceinline__ void stcs(float* p, float v) {
    asm volatile("st.global.cs.f32 [%0], %1;" :: "l"(p), "f"(v) : "memory");
}
__device__ __forceinline__ unsigned long long mkpolicy_el() {
    unsigned long long p;
    asm("createpolicy.fractional.L2::evict_last.b64 %0, 1.0;" : "=l"(p));
    return p;
}
__device__ __forceinline__ void st_el(float* p, float v, unsigned long long pol) {
    asm volatile("st.global.L2::cache_hint.f32 [%0], %1, %2;"
                 :: "l"(p), "f"(v), "l"(pol) : "memory");
}
__device__ __forceinline__ float2 ldg_el2(const float* p, unsigned long long pol) {
    float2 v;
    asm("ld.global.nc.L2::cache_hint.v2.f32 {%0,%1}, [%2], %3;"
        : "=f"(v.x), "=f"(v.y) : "l"(p), "l"(pol));
    return v;
}
__device__ __forceinline__ float ldcg(const float* p) {
    float v;
    asm volatile("ld.global.cg.f32 %0, [%1];" : "=f"(v) : "l"(p) : "memory");
    return v;
}

// DSMEM broadcast (scan): store v to smem slot of cluster CTA 'rank'
__device__ __forceinline__ void dsmem_st(uint32_t laddr, float v, int rank) {
    uint32_t raddr;
    asm("mapa.shared::cluster.u32 %0, %1, %2;" : "=r"(raddr) : "r"(laddr), "r"(rank));
    asm volatile("st.shared::cluster.f32 [%0], %1;" :: "r"(raddr), "f"(v) : "memory");
}

#define CLUSTER_SYNC() do { \
    asm volatile("barrier.cluster.arrive.aligned;" ::: "memory"); \
    asm volatile("barrier.cluster.wait.aligned;" ::: "memory"); \
} while (0)

// flat N-arrival barrier (scan epilogue only)
__device__ __forceinline__ void bar_n(unsigned* ctr, unsigned target) {
    __syncthreads();
    if (threadIdx.x == 0) {
        asm volatile("red.release.gpu.global.add.u32 [%0], %1;"
                     :: "l"(ctr), "r"(1u) : "memory");
        unsigned v;
        do {
            asm volatile("ld.acquire.gpu.global.u32 %0, [%1];"
                         : "=r"(v) : "l"(ctr) : "memory");
        } while (v < target);
    }
    __syncthreads();
}

// ---------------------------------------------------------------------------
// k_pre: global-state init + layer-0 gx GEMM (both dirs), A gathered from emb
// ---------------------------------------------------------------------------
__global__ void k_pre(const int* __restrict__ seq, const float* __restrict__ emb,
                      const float* __restrict__ B0, const float* __restrict__ B1,
                      const float* __restrict__ bias0, const float* __restrict__ bias1,
                      float* __restrict__ C0, float* __restrict__ C1) {
    __shared__ float sA[32][33];
    __shared__ float sB[32][33];
    int tx = threadIdx.x, ty = threadIdx.y;
    int tid = ty * 32 + tx;
    if (blockIdx.x == 0 && blockIdx.y == 0 && blockIdx.z == 0) {
        for (int i = tid; i < 8; i += 256) g_ctr[i] = 0u;
        for (int i = tid; i < MAXL; i += 256) g_slots[i] = 0ull;
        float* dh = &g_dh[0][0][0];
        for (int i = tid; i < 2 * 2 * 512; i += 256) dh[i] = 0.f;
    }
    const float* B = blockIdx.z ? B1 : B0;
    const float* bias = blockIdx.z ? bias1 : bias0;
    float* C = blockIdx.z ? C1 : C0;
    int n0 = blockIdx.x * 32, m0 = blockIdx.y * 32;
    float acc[4] = {0.f, 0.f, 0.f, 0.f};
    for (int k0 = 0; k0 < H; k0 += 32) {
        for (int r = ty; r < 32; r += 8) {
            int m = m0 + r, k = k0 + tx, n = n0 + r;
            int tok = __ldg(seq + m);
            sA[r][tx] = (k < H) ? __ldg(emb + (size_t)tok * H + k) : 0.f;
            sB[r][tx] = (n < H3 && k < H) ? __ldg(B + (size_t)n * H + k) : 0.f;
        }
        __syncthreads();
#pragma unroll
        for (int kk = 0; kk < 32; kk++) {
            float b = sB[tx][kk];
#pragma unroll
            for (int r = 0; r < 4; r++) acc[r] += sA[ty + 8 * r][kk] * b;
        }
        __syncthreads();
    }
    int n = n0 + tx;
    if (n < H3) {
        float bv = __ldg(bias + n);
#pragma unroll
        for (int r = 0; r < 4; r++) {
            int m = m0 + ty + 8 * r;
            C[(size_t)m * H3 + n] = acc[r] + bv;
        }
    }
}

// ---------------------------------------------------------------------------
// Dual GEMM (layer-1 gx)
// ---------------------------------------------------------------------------
__global__ void k_gemm2(const float* __restrict__ A, int lda,
                        const float* __restrict__ B0, const float* __restrict__ B1,
                        int ldb,
                        const float* __restrict__ bias0, const float* __restrict__ bias1,
                        float* __restrict__ C0, float* __restrict__ C1, int ldc,
                        int M, int N, int K) {
    const float* B = blockIdx.z ? B1 : B0;
    const float* bias = blockIdx.z ? bias1 : bias0;
    float* C = blockIdx.z ? C1 : C0;
    __shared__ float sA[32][33];
    __shared__ float sB[32][33];
    int tx = threadIdx.x, ty = threadIdx.y;
    int n0 = blockIdx.x * 32, m0 = blockIdx.y * 32;
    float acc[4] = {0.f, 0.f, 0.f, 0.f};
    for (int k0 = 0; k0 < K; k0 += 32) {
        for (int r = ty; r < 32; r += 8) {
            int m = m0 + r, k = k0 + tx, n = n0 + r;
            sA[r][tx] = (m < M && k < K) ? __ldg(A + (size_t)m * lda + k) : 0.f;
            sB[r][tx] = (n < N && k < K) ? __ldg(B + (size_t)n * ldb + k) : 0.f;
        }
        __syncthreads();
#pragma unroll
        for (int kk = 0; kk < 32; kk++) {
            float b = sB[tx][kk];
#pragma unroll
            for (int r = 0; r < 4; r++) acc[r] += sA[ty + 8 * r][kk] * b;
        }
        __syncthreads();
    }
    int n = n0 + tx;
    if (n < N) {
        float bv = __ldg(bias + n);
#pragma unroll
        for (int r = 0; r < 4; r++) {
            int m = m0 + ty + 8 * r;
            if (m < M) C[(size_t)m * ldc + n] = acc[r] + bv;
        }
    }
}

// ---------------------------------------------------------------------------
// Scan (R12, banked): one 16-CTA cluster per direction, DSMEM h-broadcast.
// ---------------------------------------------------------------------------
__global__ void __launch_bounds__(SC_THREADS, 1) k_scan(
        int layer,
        const float* __restrict__ Whhf, const float* __restrict__ Whhb,
        const float* __restrict__ bhhf, const float* __restrict__ bhhb,
        const float* __restrict__ cW) {
    extern __shared__ float sm[];
    float* sW  = sm;
    float* sh0 = sm + SC_UPC * 3 * H;
    float* sh1 = sh0 + 512;
    int dir = blockIdx.x >> 4;
    int cta = blockIdx.x & 15;
    int tid = threadIdx.x, wid = tid >> 5, lane = tid & 31;
    const float* gx  = dir ? g_gxb : g_gxf;
    const float* Whh = dir ? Whhb : Whhf;
    const float* bhh = dir ? bhhb : bhhf;
    float* y;
    int ystride;
    float* hfin = nullptr;
    if (layer == 0) {
        y = g_x1 + (dir ? H : 0);
        ystride = 2 * H;
        hfin = &g_dh[0][dir][0];
    } else {
        y = dir ? g_y1b : g_y1f;
        ystride = H;
    }
    int u = cta * SC_UPC + wid;
    bool uval = (u < H);

    if (uval) {
#pragma unroll
        for (int r = 0; r < 3; r++) {
            const float* src = Whh + (size_t)(u + r * H) * H;
            float* dst = sW + (wid * 3 + r) * H;
            for (int i = lane; i < H; i += 32) dst[i] = __ldg(src + i);
        }
    }
    float b0 = 0.f, b1 = 0.f, b2 = 0.f;
    if (uval) {
        b0 = __ldg(bhh + u); b1 = __ldg(bhh + H + u); b2 = __ldg(bhh + 2 * H + u);
    }
    if (tid < 1024) {
        if (tid < 512) sh0[tid] = 0.f; else sh1[tid - 512] = 0.f;
    }
    __syncthreads();
    CLUSTER_SYNC();

    const float4* w0 = (const float4*)(sW + (wid * 3 + 0) * H);
    const float4* w1 = (const float4*)(sW + (wid * 3 + 1) * H);
    const float4* w2 = (const float4*)(sW + (wid * 3 + 2) * H);

    for (int step = 0; step < S; step++) {
        int t = dir ? (S - 1 - step) : step;
        float* shr = (step & 1) ? sh1 : sh0;
        float* shw = (step & 1) ? sh0 : sh1;
        if (uval) {
            const float4* hp = (const float4*)shr;
            float a0 = 0.f, a1 = 0.f, a2 = 0.f;
            for (int c = lane; c < 125; c += 32) {
                float4 hv = hp[c];
                float4 m0 = w0[c], m1 = w1[c], m2 = w2[c];
                a0 += m0.x * hv.x + m0.y * hv.y + m0.z * hv.z + m0.w * hv.w;
                a1 += m1.x * hv.x + m1.y * hv.y + m1.z * hv.z + m1.w * hv.w;
                a2 += m2.x * hv.x + m2.y * hv.y + m2.z * hv.z + m2.w * hv.w;
            }
            __syncwarp();
            a0 = wred(a0); a1 = wred(a1); a2 = wred(a2);
            float h2 = 0.f;
            if (lane == 0) {
                const float* g = gx + (size_t)t * H3;
                float r = sigf(__ldg(g + u) + a0 + b0);
                float z = sigf(__ldg(g + H + u) + a1 + b1);
                float n = tanhf(__ldg(g + 2 * H + u) + r * (a2 + b2));
                h2 = (1.f - z) * n + z * shr[u];
            }
            h2 = __shfl_sync(0xffffffffu, h2, 0);
            if (lane < 16) {
                uint32_t laddr = (uint32_t)__cvta_generic_to_shared(&shw[u]);
                dsmem_st(laddr, h2, lane);
            }
            if (lane == 0) {
                y[(size_t)t * ystride + u] = h2;
                if (layer == 0 && step == S - 1) stcg(hfin + u, h2);
            }
        }
        CLUSTER_SYNC();
    }

    if (layer == 1) {
        unsigned* ectr = &g_ctr[5];
        unsigned er = 0;
        bar_n(ectr, (++er) * 2 * SC_CPD);
        for (int i = blockIdx.x * SC_THREADS + tid; i < S * H;
             i += 2 * SC_CPD * SC_THREADS)
            stcg(g_enc + i, ldcg(g_y1f + i) + ldcg(g_y1b + i));
        bar_n(ectr, (++er) * 2 * SC_CPD);
        {
            int grpi = tid >> 8;
            int gt = tid & 255;
            int tx = gt & 31, ty = gt >> 5;
            float* sA = sm + grpi * (2 * 32 * 33);
            float* sB = sA + 32 * 33;
            int tile = blockIdx.x * 4 + grpi;
            int m0 = (tile >> 4) * 32, n0 = (tile & 15) * 32;
            float acc[4] = {0.f, 0.f, 0.f, 0.f};
            for (int k0 = 0; k0 < H; k0 += 32) {
                for (int r = ty; r < 32; r += 8) {
                    int m = m0 + r, k = k0 + tx, n = n0 + r;
                    sA[r * 33 + tx] = (m < S && k < H)
                        ? ldcg(g_enc + (size_t)m * H + k) : 0.f;
                    sB[r * 33 + tx] = (n < H && k < H)
                        ? __ldg(cW + (size_t)n * (2 * H) + H + k) : 0.f;
                }
                __syncthreads();
#pragma unroll
                for (int kk = 0; kk < 32; kk++) {
                    float b = sB[tx * 33 + kk];
#pragma unroll
                    for (int r = 0; r < 4; r++)
                        acc[r] += sA[(ty + 8 * r) * 33 + kk] * b;
                }
                __syncthreads();
            }
            int n = n0 + tx;
            if (n < H) {
#pragma unroll
                for (int r = 0; r < 4; r++) {
                    int m = m0 + ty + 8 * r;
                    if (m < S) stcg(g_P + (size_t)m * H + n, acc[r]);
                }
            }
        }
        bar_n(ectr, (++er) * 2 * SC_CPD);
        for (int i = blockIdx.x * SC_THREADS + tid; i < H * S;
             i += 2 * SC_CPD * SC_THREADS) {
            int j = i >> 8, s = i & 255;
            g_PT[i] = ldcg(g_P + (size_t)s * H + j);
        }
    }
    CLUSTER_SYNC();
}

// ---------------------------------------------------------------------------
// k_oWT: transpose oW (VxH) -> g_oWT (HxVP), stores primed evict_last
// ---------------------------------------------------------------------------
__global__ void __launch_bounds__(DEC_THREADS) k_oWT(const float* __restrict__ oW) {
    __shared__ float stile[32][33];
    int tid = threadIdx.x;
    unsigned long long pol = mkpolicy_el();
    int tx = tid & 31, ty4 = (tid >> 5) * 4;
    int ntile = ((V + 31) / 32) * 16;
    for (int tile = blockIdx.x; tile < ntile; tile += DEC_CTAS) {
        int tj = tile >> 4, tk = tile & 15;
        __syncthreads();
#pragma unroll
        for (int r = 0; r < 4; r++) {
            int jj = ty4 + r;
            int j = tj * 32 + jj, k = tk * 32 + tx;
            stile[jj][tx] = (j < V && k < H) ? __ldg(oW + (size_t)j * H + k) : 0.f;
        }
        __syncthreads();
#pragma unroll
        for (int r = 0; r < 4; r++) {
            int kk = ty4 + r;
            int k = tk * 32 + kk, j = tj * 32 + tx;
            if (k < H) st_el(&g_oWT[(size_t)k * VP + j], stile[tx][kk], pol);
        }
    }
}

// ---------------------------------------------------------------------------
// Decoder step kernels (graph-sequenced; launch boundary = sync + ordering)
// ---------------------------------------------------------------------------

// GRU cell, warp per unit, weights streamed from L2. grid 63 x 256.
__global__ void __launch_bounds__(256) k_dcell(
        int layer, int t,
        const float* __restrict__ emb,
        const float* __restrict__ Wih, const float* __restrict__ Whh,
        const float* __restrict__ bih, const float* __restrict__ bhh) {
    __shared__ __align__(16) float sx[512];
    __shared__ __align__(16) float sh[512];
    int tid = threadIdx.x, wid = tid >> 5, lane = tid & 31;
    int p = t & 1;
    const float* xg;
    if (layer == 0) {
        int tok = SOS;
        if (t > 0) {
            unsigned long long pk = g_slots[t - 1];
            tok = (int)(~(unsigned)(pk & 0xFFFFFFFFull));
        }
        xg = emb + (size_t)tok * H;
    } else {
        xg = &g_dh[1 - p][0][0];
    }
    const float* hg = &g_dh[p][layer][0];
    for (int i = tid; i < 512; i += 256) {
        sx[i] = (i < H) ? xg[i] : 0.f;
        sh[i] = hg[i];                 // tail units stay 0 forever
    }
    __syncthreads();
    int u = blockIdx.x * 8 + wid;
    if (u >= H) return;

    const float4* xp = (const float4*)sx;
    const float4* hp = (const float4*)sh;
    const float4* w0 = (const float4*)(Wih + (size_t)u * H);
    const float4* w1 = (const float4*)(Wih + (size_t)(u + H) * H);
    const float4* w2 = (const float4*)(Wih + (size_t)(u + 2 * H) * H);
    const float4* w3 = (const float4*)(Whh + (size_t)u * H);
    const float4* w4 = (const float4*)(Whh + (size_t)(u + H) * H);
    const float4* w5 = (const float4*)(Whh + (size_t)(u + 2 * H) * H);
    float a0 = 0.f, a1 = 0.f, a2 = 0.f, a3 = 0.f, a4 = 0.f, a5 = 0.f;
    for (int c = lane; c < 125; c += 32) {
        float4 xv = xp[c], hv = hp[c];
        float4 m0 = __ldg(w0 + c), m1 = __ldg(w1 + c), m2 = __ldg(w2 + c);
        float4 m3 = __ldg(w3 + c), m4 = __ldg(w4 + c), m5 = __ldg(w5 + c);
        a0 += m0.x * xv.x + m0.y * xv.y + m0.z * xv.z + m0.w * xv.w;
        a1 += m1.x * xv.x + m1.y * xv.y + m1.z * xv.z + m1.w * xv.w;
        a2 += m2.x * xv.x + m2.y * xv.y + m2.z * xv.z + m2.w * xv.w;
        a3 += m3.x * hv.x + m3.y * hv.y + m3.z * hv.z + m3.w * hv.w;
        a4 += m4.x * hv.x + m4.y * hv.y + m4.z * hv.z + m4.w * hv.w;
        a5 += m5.x * hv.x + m5.y * hv.y + m5.z * hv.z + m5.w * hv.w;
    }
    __syncwarp();
    a0 = wred(a0); a1 = wred(a1); a2 = wred(a2);
    a3 = wred(a3); a4 = wred(a4); a5 = wred(a5);
    if (lane == 0) {
        float r = sigf(a0 + __ldg(bih + u) + a3 + __ldg(bhh + u));
        float z = sigf(a1 + __ldg(bih + H + u) + a4 + __ldg(bhh + H + u));
        float n = tanhf(a2 + __ldg(bih + 2 * H + u) +
                        r * (a5 + __ldg(bhh + 2 * H + u)));
        g_dh[1 - p][layer][u] = (1.f - z) * n + z * sh[u];
    }
}

// attention scores + Wc1@rnn. grid 128 x 256.
__global__ void __launch_bounds__(256) k_dattn(int t, const float* __restrict__ cW) {
    __shared__ __align__(16) float sh[512];
    int tid = threadIdx.x, wid = tid >> 5, lane = tid & 31;
    int p = t & 1;
    const float* hg = &g_dh[1 - p][1][0];
    for (int i = tid; i < 512; i += 256) sh[i] = hg[i];
    __syncthreads();
    const float4* rp = (const float4*)sh;
    if (wid < 2) {
        int sidx = blockIdx.x * 2 + wid;
        const float4* ep = (const float4*)(g_enc + (size_t)sidx * H);
        float a = 0.f;
        for (int c = lane; c < 125; c += 32) {
            float4 ev = __ldg(ep + c);
            float4 rv = rp[c];
            a += ev.x * rv.x + ev.y * rv.y + ev.z * rv.z + ev.w * rv.w;
        }
        __syncwarp();
        a = wred(a);
        if (lane == 0) g_scores[sidx] = a;
    } else if (wid < 6) {
        int uc = blockIdx.x * 4 + (wid - 2);
        if (uc < H) {
            const float4* wc = (const float4*)(cW + (size_t)uc * 2 * H);
            float a = 0.f;
            for (int c = lane; c < 125; c += 32) {
                float4 wv = __ldg(wc + c);
                float4 rv = rp[c];
                a += wv.x * rv.x + wv.y * rv.y + wv.z * rv.z + wv.w * rv.w;
            }
            __syncwarp();
            a = wred(a);
            if (lane == 0) g_wc[uc] = a;
        }
    }
}

// softmax over scores + combined c. grid 125 x 256.
__global__ void __launch_bounds__(256) k_dsoft(const float* __restrict__ cb) {
    __shared__ float se[S];
    __shared__ float sred[32];
    int tid = threadIdx.x, wid = tid >> 5, lane = tid & 31;
    float sc = g_scores[tid];
    float m = sc;
#pragma unroll
    for (int o = 16; o; o >>= 1) m = fmaxf(m, __shfl_xor_sync(0xffffffffu, m, o));
    if (lane == 0) sred[wid] = m;
    __syncthreads();
    float bm = sred[0];
#pragma unroll
    for (int i = 1; i < 8; i++) bm = fmaxf(bm, sred[i]);
    float e = expf(sc - bm);
    se[tid] = e;
    float sl = wred(e);
    __syncthreads();
    if (lane == 0) sred[16 + wid] = sl;
    __syncthreads();
    float sumE = sred[16];
#pragma unroll
    for (int i = 1; i < 8; i++) sumE += sred[16 + i];

    if (wid < 4) {
        int uc = blockIdx.x * 4 + wid;
        if (uc < H) {
            const float4* ptp = (const float4*)(g_PT + (size_t)uc * S);
            float a2 = 0.f;
            for (int c = lane; c < 64; c += 32) {
                float4 pv = __ldg(ptp + c);
                a2 += pv.x * se[c * 4] + pv.y * se[c * 4 + 1] +
                      pv.z * se[c * 4 + 2] + pv.w * se[c * 4 + 3];
            }
            __syncwarp();
            a2 = wred(a2);
            if (lane == 0)
                g_c[uc] = tanhf(g_wc[uc] + a2 / sumE + __ldg(cb + uc));
        }
    }
}

// logits + fused argmax. grid 128 x 256.
__global__ void __launch_bounds__(DEC_THREADS) k_dlogits(
        int t, const float* __restrict__ ob) {
    __shared__ __align__(16) float sc_c[512];
    __shared__ unsigned long long swb[8];
    int tid = threadIdx.x, wid = tid >> 5, lane = tid & 31;
    unsigned long long pol = mkpolicy_el();
    for (int i = tid; i < 512; i += DEC_THREADS)
        sc_c[i] = (i < H) ? g_c[i] : 0.f;
    __syncthreads();
    int gtid = blockIdx.x * DEC_THREADS + tid;
    int col = gtid << 1;
    unsigned long long pk = 0ull;
    if (col < V) {
        bool has1 = (col + 1 < V);
        float acc0 = __ldg(ob + col);
        float acc1 = has1 ? __ldg(ob + col + 1) : 0.f;
        const float* wp = g_oWT + col;
#pragma unroll 1
        for (int k = 0; k < H; k += 4) {
            float2 w0 = ldg_el2(wp, pol);
            float2 w1 = ldg_el2(wp + VP, pol);
            float2 w2 = ldg_el2(wp + 2 * (size_t)VP, pol);
            float2 w3 = ldg_el2(wp + 3 * (size_t)VP, pol);
            float c0 = sc_c[k], c1 = sc_c[k + 1];
            float c2 = sc_c[k + 2], c3 = sc_c[k + 3];
            acc0 += c0 * w0.x + c1 * w1.x + c2 * w2.x + c3 * w3.x;
            acc1 += c0 * w0.y + c1 * w1.y + c2 * w2.y + c3 * w3.y;
            wp += 4 * (size_t)VP;
        }
        float* lrow = g_logits + (size_t)t * V;
        stcs(lrow + col, acc0);
        pk = ((unsigned long long)fflip(acc0) << 32) | (unsigned)(~(unsigned)col);
        if (has1) {
            stcs(lrow + col + 1, acc1);
            unsigned long long pk2 =
                ((unsigned long long)fflip(acc1) << 32) |
                (unsigned)(~(unsigned)(col + 1));
            if (pk2 > pk) pk = pk2;
        }
    }
#pragma unroll
    for (int o = 16; o; o >>= 1) {
        unsigned long long other = __shfl_xor_sync(0xffffffffu, pk, o);
        if (other > pk) pk = other;
    }
    if (lane == 0) swb[wid] = pk;
    __syncthreads();
    if (tid == 0) {
        unsigned long long b = swb[0];
#pragma unroll
        for (int i = 1; i < 8; i++) if (swb[i] > b) b = swb[i];
        atomicMax(&g_slots[t], b);
    }
}

// ---------------------------------------------------------------------------
// Final softmax over stored logits + token output
// ---------------------------------------------------------------------------
__global__ void k_probs(float* __restrict__ out_probs, float* __restrict__ out_tok) {
    int t = blockIdx.x;
    int tid = threadIdx.x, wid = tid >> 5, lane = tid & 31;
    __shared__ float sred[32];
    __shared__ float stot;
    const float* lrow = g_logits + (size_t)t * V;
    unsigned long long sl64 = g_slots[t];
    float mx = unflip((unsigned)(sl64 >> 32));
    if (tid == 0 && out_tok)
        out_tok[t] = (float)(int)(~(unsigned)(sl64 & 0xFFFFFFFFull));
    float s = 0.f;
    for (int i = tid; i < V; i += blockDim.x) s += expf(lrow[i] - mx);
    s = wred(s);
    if (lane == 0) sred[wid] = s;
    __syncthreads();
    if (tid == 0) {
        float tt = 0.f;
#pragma unroll
        for (int i = 0; i < 32; i++) tt += sred[i];
        stot = tt;
    }
    __syncthreads();
    float inv = 1.f / stot;
    float* orow = out_probs + (size_t)t * V;
    for (int i = tid; i < V; i += blockDim.x) orow[i] = expf(lrow[i] - mx) * inv;
}

// ---------------------------------------------------------------------------
// Host launcher — decoder fully unrolled into graph-sequenced launches
// ---------------------------------------------------------------------------
extern "C" void kernel_launch(void* const* d_in, const int* in_sizes, int n_in,
                              void* d_out, int out_size) {
    const int* seq = (const int*)d_in[0];
    int i = 1;
    while (i < n_in && in_sizes[i] == 1) i++;
    const float* emb = (const float*)d_in[i++];
    const float* eW[4][4];
    for (int e = 0; e < 4; e++)
        for (int w = 0; w < 4; w++) eW[e][w] = (const float*)d_in[i++];
    const float* dWih = (const float*)d_in[i++];
    const float* dWhh = (const float*)d_in[i++];
    const float* dbih = (const float*)d_in[i++];
    const float* dbhh = (const float*)d_in[i++];
    const float* cW   = (const float*)d_in[i++];
    const float* cb   = (const float*)d_in[i++];
    const float* oW   = (const float*)d_in[i++];
    const float* ob   = (const float*)d_in[i++];

    float* out = (float*)d_out;
    int has_tok = (out_size >= MAXL * V + MAXL);
    float* out_tok = has_tok ? out : nullptr;
    float* out_probs = out + (has_tok ? MAXL : 0);

    int scan_smem = (SC_UPC * 3 * H + 1024) * 4;
    cudaFuncSetAttribute(k_scan, cudaFuncAttributeMaxDynamicSharedMemorySize,
                         scan_smem);
    cudaFuncSetAttribute(k_scan, cudaFuncAttributeNonPortableClusterSizeAllowed, 1);

    void *p_gxf, *p_gxb, *p_x1;
    cudaGetSymbolAddress(&p_gxf, g_gxf);
    cudaGetSymbolAddress(&p_gxb, g_gxb);
    cudaGetSymbolAddress(&p_x1, g_x1);

    cudaLaunchConfig_t scfg = {};
    scfg.gridDim = dim3(2 * SC_CPD, 1, 1);
    scfg.blockDim = dim3(SC_THREADS, 1, 1);
    scfg.dynamicSmemBytes = scan_smem;
    scfg.stream = 0;
    cudaLaunchAttribute sattr[1];
    sattr[0].id = cudaLaunchAttributeClusterDimension;
    sattr[0].val.clusterDim.x = SC_CPD;
    sattr[0].val.clusterDim.y = 1;
    sattr[0].val.clusterDim.z = 1;
    scfg.attrs = sattr;
    scfg.numAttrs = 1;

    dim3 tb(32, 8);
    // encoder
    k_pre<<<dim3(47, 8, 2), tb>>>(seq, emb, eW[0][0], eW[1][0],
                                  eW[0][2], eW[1][2],
                                  (float*)p_gxf, (float*)p_gxb);
    cudaLaunchKernelEx(&scfg, k_scan, 0, eW[0][1], eW[1][1],
                       eW[0][3], eW[1][3], cW);
    k_gemm2<<<dim3((H3 + 31) / 32, (S + 31) / 32, 2), tb>>>(
        (const float*)p_x1, 2 * H, eW[2][0], eW[3][0], 2 * H, eW[2][2], eW[3][2],
        (float*)p_gxf, (float*)p_gxb, H3, S, H3, 2 * H);
    cudaLaunchKernelEx(&scfg, k_scan, 1, eW[2][1], eW[3][1],
                       eW[2][3], eW[3][3], cW);
    // oWT transpose (once)
    k_oWT<<<DEC_CTAS, DEC_THREADS>>>(oW);

    // decoder: 64 steps x 5 graph-sequenced launches
    for (int t = 0; t < MAXL; t++) {
        k_dcell<<<63, 256>>>(0, t, emb, dWih, dWhh, dbih, dbhh);
        k_dcell<<<63, 256>>>(1, t, emb, dWih + (size_t)H3 * H,
                             dWhh + (size_t)H3 * H, dbih + H3, dbhh + H3);
        k_dattn<<<128, 256>>>(t, cW);
        k_dsoft<<<125, 256>>>(cb);
        k_dlogits<<<128, 256>>>(t, ob);
    }
    // probs + tokens
    k_probs<<<MAXL, 1024>>>(out_probs, out_tok);
}

// round 14
// speedup vs baseline: 1.5824x; 1.5824x over previous
#include <cuda_runtime.h>
#include <stdint.h>
#include <math.h>

#define H      500
#define H3     1500
#define S      256
#define V      50257
#define VP     50272            // V padded (128B row alignment)
#define MAXL   64
#define SOS    1
#define CLU    8                // decoder cluster size

// scan: 16 CTAs per direction = ONE 16-CTA cluster, 1024 threads, warp-per-unit
#define SC_CPD     16
#define SC_THREADS 1024
#define SC_UPC     32

#define DEC_CTAS     128
#define DEC_THREADS  256
#define DUPC         8
#define NCLUST       16

// ---------------------------------------------------------------------------
// Device scratch
// ---------------------------------------------------------------------------
__device__ float g_gxf[S * H3];
__device__ float g_gxb[S * H3];
__device__ float g_x1[S * 2 * H];
__device__ float g_y1f[S * H];
__device__ float g_y1b[S * H];
__device__ float g_enc[S * H];
__device__ float g_P[S * H];
__device__ float g_PT[H * S];
__device__ float g_dh[2][2][512];      // [parity][layer][unit]
__device__ float g_scores[S];
__device__ float g_wc[512];
__device__ float g_c[512];
__device__ float g_oWT[(size_t)H * VP];
__device__ float g_logits[(size_t)MAXL * V];
__device__ unsigned long long g_slots[MAXL];
__device__ unsigned g_ctr[8];
// ctr map: 4 decoder, 5 scan epilogue

// ---------------------------------------------------------------------------
// Helpers
// ---------------------------------------------------------------------------
__device__ __forceinline__ float sigf(float x) { return 1.f / (1.f + expf(-x)); }

__device__ __forceinline__ float wred(float v) {
#pragma unroll
    for (int o = 16; o; o >>= 1) v += __shfl_xor_sync(0xffffffffu, v, o);
    return v;
}

__device__ __forceinline__ unsigned fflip(float f) {
    unsigned u = __float_as_uint(f);
    return (u & 0x80000000u) ? ~u : (u | 0x80000000u);
}
__device__ __forceinline__ float unflip(unsigned u) {
    return (u & 0x80000000u) ? __uint_as_float(u ^ 0x80000000u)
                             : __uint_as_float(~u);
}

__device__ __forceinline__ void stcg(float* p, float v) {
    asm volatile("st.global.cg.f32 [%0], %1;" :: "l"(p), "f"(v) : "memory");
}
__device__ __forceinline__ void stcs(float* p, float v) {
    asm volatile("st.global.cs.f32 [%0], %1;" :: "l"(p), "f"(v) : "memory");
}
__device__ __forceinline__ unsigned long long mkpolicy_el() {
    unsigned long long p;
    asm("createpolicy.fractional.L2::evict_last.b64 %0, 1.0;" : "=l"(p));
    return p;
}
__device__ __forceinline__ void st_el(float* p, float v, unsigned long long pol) {
    asm volatile("st.global.L2::cache_hint.f32 [%0], %1, %2;"
                 :: "l"(p), "f"(v), "l"(pol) : "memory");
}
__device__ __forceinline__ float2 ldg_el2(const float* p, unsigned long long pol) {
    float2 v;
    asm("ld.global.nc.L2::cache_hint.v2.f32 {%0,%1}, [%2], %3;"
        : "=f"(v.x), "=f"(v.y) : "l"(p), "l"(pol));
    return v;
}
__device__ __forceinline__ float ldcg(const float* p) {
    float v;
    asm volatile("ld.global.cg.f32 %0, [%1];" : "=f"(v) : "l"(p) : "memory");
    return v;
}
__device__ __forceinline__ unsigned long long ldcg_u64(const unsigned long long* p) {
    unsigned long long v;
    asm volatile("ld.global.cg.u64 %0, [%1];" : "=l"(v) : "l"(p) : "memory");
    return v;
}

// DSMEM broadcast: store v to sh-slot (local smem address laddr) of cluster CTA 'rank'
__device__ __forceinline__ void dsmem_st(uint32_t laddr, float v, int rank) {
    uint32_t raddr;
    asm("mapa.shared::cluster.u32 %0, %1, %2;" : "=r"(raddr) : "r"(laddr), "r"(rank));
    asm volatile("st.shared::cluster.f32 [%0], %1;" :: "r"(raddr), "f"(v) : "memory");
}

#define CLUSTER_SYNC() do { \
    asm volatile("barrier.cluster.arrive.aligned;" ::: "memory"); \
    asm volatile("barrier.cluster.wait.aligned;" ::: "memory"); \
} while (0)

// flat N-arrival barrier (release/acquire)
__device__ __forceinline__ void bar_n(unsigned* ctr, unsigned target) {
    __syncthreads();
    if (threadIdx.x == 0) {
        asm volatile("red.release.gpu.global.add.u32 [%0], %1;"
                     :: "l"(ctr), "r"(1u) : "memory");
        unsigned v;
        do {
            asm volatile("ld.acquire.gpu.global.u32 %0, [%1];"
                         : "=r"(v) : "l"(ctr) : "memory");
        } while (v < target);
    }
    __syncthreads();
}

// hierarchical barrier for the 128-CTA decoder (16 clusters of 8)
__device__ __forceinline__ void hbar(unsigned* ctr, unsigned target) {
    asm volatile("barrier.cluster.arrive.aligned;" ::: "memory");
    asm volatile("barrier.cluster.wait.aligned;" ::: "memory");
    unsigned rank;
    asm("mov.u32 %0, %%cluster_ctarank;" : "=r"(rank));
    if (rank == 0 && threadIdx.x == 0) {
        asm volatile("red.release.gpu.global.add.u32 [%0], %1;"
                     :: "l"(ctr), "r"(1u) : "memory");
        unsigned v;
        do {
            asm volatile("ld.acquire.gpu.global.u32 %0, [%1];"
                         : "=r"(v) : "l"(ctr) : "memory");
        } while (v < target);
    }
    asm volatile("barrier.cluster.arrive.aligned;" ::: "memory");
    asm volatile("barrier.cluster.wait.aligned;" ::: "memory");
}

// ---------------------------------------------------------------------------
// k_pre: global-state init + layer-0 gx GEMM (both dirs), A gathered from emb
// ---------------------------------------------------------------------------
__global__ void k_pre(const int* __restrict__ seq, const float* __restrict__ emb,
                      const float* __restrict__ B0, const float* __restrict__ B1,
                      const float* __restrict__ bias0, const float* __restrict__ bias1,
                      float* __restrict__ C0, float* __restrict__ C1) {
    __shared__ float sA[32][33];
    __shared__ float sB[32][33];
    int tx = threadIdx.x, ty = threadIdx.y;
    int tid = ty * 32 + tx;
    if (blockIdx.x == 0 && blockIdx.y == 0 && blockIdx.z == 0) {
        for (int i = tid; i < 8; i += 256) g_ctr[i] = 0u;
        for (int i = tid; i < MAXL; i += 256) g_slots[i] = 0ull;
        float* dh = &g_dh[0][0][0];
        for (int i = tid; i < 2 * 2 * 512; i += 256) dh[i] = 0.f;
    }
    const float* B = blockIdx.z ? B1 : B0;
    const float* bias = blockIdx.z ? bias1 : bias0;
    float* C = blockIdx.z ? C1 : C0;
    int n0 = blockIdx.x * 32, m0 = blockIdx.y * 32;
    float acc[4] = {0.f, 0.f, 0.f, 0.f};
    for (int k0 = 0; k0 < H; k0 += 32) {
        for (int r = ty; r < 32; r += 8) {
            int m = m0 + r, k = k0 + tx, n = n0 + r;
            int tok = __ldg(seq + m);
            sA[r][tx] = (k < H) ? __ldg(emb + (size_t)tok * H + k) : 0.f;
            sB[r][tx] = (n < H3 && k < H) ? __ldg(B + (size_t)n * H + k) : 0.f;
        }
        __syncthreads();
#pragma unroll
        for (int kk = 0; kk < 32; kk++) {
            float b = sB[tx][kk];
#pragma unroll
            for (int r = 0; r < 4; r++) acc[r] += sA[ty + 8 * r][kk] * b;
        }
        __syncthreads();
    }
    int n = n0 + tx;
    if (n < H3) {
        float bv = __ldg(bias + n);
#pragma unroll
        for (int r = 0; r < 4; r++) {
            int m = m0 + ty + 8 * r;
            C[(size_t)m * H3 + n] = acc[r] + bv;
        }
    }
}

// ---------------------------------------------------------------------------
// Dual GEMM (layer-1 gx)
// ---------------------------------------------------------------------------
__global__ void k_gemm2(const float* __restrict__ A, int lda,
                        const float* __restrict__ B0, const float* __restrict__ B1,
                        int ldb,
                        const float* __restrict__ bias0, const float* __restrict__ bias1,
                        float* __restrict__ C0, float* __restrict__ C1, int ldc,
                        int M, int N, int K) {
    const float* B = blockIdx.z ? B1 : B0;
    const float* bias = blockIdx.z ? bias1 : bias0;
    float* C = blockIdx.z ? C1 : C0;
    __shared__ float sA[32][33];
    __shared__ float sB[32][33];
    int tx = threadIdx.x, ty = threadIdx.y;
    int n0 = blockIdx.x * 32, m0 = blockIdx.y * 32;
    float acc[4] = {0.f, 0.f, 0.f, 0.f};
    for (int k0 = 0; k0 < K; k0 += 32) {
        for (int r = ty; r < 32; r += 8) {
            int m = m0 + r, k = k0 + tx, n = n0 + r;
            sA[r][tx] = (m < M && k < K) ? __ldg(A + (size_t)m * lda + k) : 0.f;
            sB[r][tx] = (n < N && k < K) ? __ldg(B + (size_t)n * ldb + k) : 0.f;
        }
        __syncthreads();
#pragma unroll
        for (int kk = 0; kk < 32; kk++) {
            float b = sB[tx][kk];
#pragma unroll
            for (int r = 0; r < 4; r++) acc[r] += sA[ty + 8 * r][kk] * b;
        }
        __syncthreads();
    }
    int n = n0 + tx;
    if (n < N) {
        float bv = __ldg(bias + n);
#pragma unroll
        for (int r = 0; r < 4; r++) {
            int m = m0 + ty + 8 * r;
            if (m < M) C[(size_t)m * ldc + n] = acc[r] + bv;
        }
    }
}

// ---------------------------------------------------------------------------
// Scan: one 16-CTA cluster per direction, DSMEM h-broadcast (R12, banked).
// ---------------------------------------------------------------------------
__global__ void __launch_bounds__(SC_THREADS, 1) k_scan(
        int layer,
        const float* __restrict__ Whhf, const float* __restrict__ Whhb,
        const float* __restrict__ bhhf, const float* __restrict__ bhhb,
        const float* __restrict__ cW) {
    extern __shared__ float sm[];
    float* sW  = sm;
    float* sh0 = sm + SC_UPC * 3 * H;
    float* sh1 = sh0 + 512;
    int dir = blockIdx.x >> 4;
    int cta = blockIdx.x & 15;
    int tid = threadIdx.x, wid = tid >> 5, lane = tid & 31;
    const float* gx  = dir ? g_gxb : g_gxf;
    const float* Whh = dir ? Whhb : Whhf;
    const float* bhh = dir ? bhhb : bhhf;
    float* y;
    int ystride;
    float* hfin = nullptr;
    if (layer == 0) {
        y = g_x1 + (dir ? H : 0);
        ystride = 2 * H;
        hfin = &g_dh[0][dir][0];
    } else {
        y = dir ? g_y1b : g_y1f;
        ystride = H;
    }
    int u = cta * SC_UPC + wid;
    bool uval = (u < H);

    if (uval) {
#pragma unroll
        for (int r = 0; r < 3; r++) {
            const float* src = Whh + (size_t)(u + r * H) * H;
            float* dst = sW + (wid * 3 + r) * H;
            for (int i = lane; i < H; i += 32) dst[i] = __ldg(src + i);
        }
    }
    float b0 = 0.f, b1 = 0.f, b2 = 0.f;
    if (uval) {
        b0 = __ldg(bhh + u); b1 = __ldg(bhh + H + u); b2 = __ldg(bhh + 2 * H + u);
    }
    if (tid < 1024) {
        if (tid < 512) sh0[tid] = 0.f; else sh1[tid - 512] = 0.f;
    }
    __syncthreads();
    CLUSTER_SYNC();

    const float4* w0 = (const float4*)(sW + (wid * 3 + 0) * H);
    const float4* w1 = (const float4*)(sW + (wid * 3 + 1) * H);
    const float4* w2 = (const float4*)(sW + (wid * 3 + 2) * H);

    for (int step = 0; step < S; step++) {
        int t = dir ? (S - 1 - step) : step;
        float* shr = (step & 1) ? sh1 : sh0;
        float* shw = (step & 1) ? sh0 : sh1;
        if (uval) {
            const float4* hp = (const float4*)shr;
            float a0 = 0.f, a1 = 0.f, a2 = 0.f;
            for (int c = lane; c < 125; c += 32) {
                float4 hv = hp[c];
                float4 m0 = w0[c], m1 = w1[c], m2 = w2[c];
                a0 += m0.x * hv.x + m0.y * hv.y + m0.z * hv.z + m0.w * hv.w;
                a1 += m1.x * hv.x + m1.y * hv.y + m1.z * hv.z + m1.w * hv.w;
                a2 += m2.x * hv.x + m2.y * hv.y + m2.z * hv.z + m2.w * hv.w;
            }
            __syncwarp();
            a0 = wred(a0); a1 = wred(a1); a2 = wred(a2);
            float h2 = 0.f;
            if (lane == 0) {
                const float* g = gx + (size_t)t * H3;
                float r = sigf(__ldg(g + u) + a0 + b0);
                float z = sigf(__ldg(g + H + u) + a1 + b1);
                float n = tanhf(__ldg(g + 2 * H + u) + r * (a2 + b2));
                h2 = (1.f - z) * n + z * shr[u];
            }
            h2 = __shfl_sync(0xffffffffu, h2, 0);
            if (lane < 16) {
                uint32_t laddr = (uint32_t)__cvta_generic_to_shared(&shw[u]);
                dsmem_st(laddr, h2, lane);
            }
            if (lane == 0) {
                y[(size_t)t * ystride + u] = h2;
                if (layer == 0 && step == S - 1) stcg(hfin + u, h2);
            }
        }
        CLUSTER_SYNC();
    }

    if (layer == 1) {
        unsigned* ectr = &g_ctr[5];
        unsigned er = 0;
        bar_n(ectr, (++er) * 2 * SC_CPD);
        for (int i = blockIdx.x * SC_THREADS + tid; i < S * H;
             i += 2 * SC_CPD * SC_THREADS)
            stcg(g_enc + i, ldcg(g_y1f + i) + ldcg(g_y1b + i));
        bar_n(ectr, (++er) * 2 * SC_CPD);
        {
            int grpi = tid >> 8;
            int gt = tid & 255;
            int tx = gt & 31, ty = gt >> 5;
            float* sA = sm + grpi * (2 * 32 * 33);
            float* sB = sA + 32 * 33;
            int tile = blockIdx.x * 4 + grpi;
            int m0 = (tile >> 4) * 32, n0 = (tile & 15) * 32;
            float acc[4] = {0.f, 0.f, 0.f, 0.f};
            for (int k0 = 0; k0 < H; k0 += 32) {
                for (int r = ty; r < 32; r += 8) {
                    int m = m0 + r, k = k0 + tx, n = n0 + r;
                    sA[r * 33 + tx] = (m < S && k < H)
                        ? ldcg(g_enc + (size_t)m * H + k) : 0.f;
                    sB[r * 33 + tx] = (n < H && k < H)
                        ? __ldg(cW + (size_t)n * (2 * H) + H + k) : 0.f;
                }
                __syncthreads();
#pragma unroll
                for (int kk = 0; kk < 32; kk++) {
                    float b = sB[tx * 33 + kk];
#pragma unroll
                    for (int r = 0; r < 4; r++)
                        acc[r] += sA[(ty + 8 * r) * 33 + kk] * b;
                }
                __syncthreads();
            }
            int n = n0 + tx;
            if (n < H) {
#pragma unroll
                for (int r = 0; r < 4; r++) {
                    int m = m0 + ty + 8 * r;
                    if (m < S) stcg(g_P + (size_t)m * H + n, acc[r]);
                }
            }
        }
        bar_n(ectr, (++er) * 2 * SC_CPD);
        for (int i = blockIdx.x * SC_THREADS + tid; i < H * S;
             i += 2 * SC_CPD * SC_THREADS) {
            int j = i >> 8, s = i & 255;
            g_PT[i] = ldcg(g_P + (size_t)s * H + j);
        }
    }
    CLUSTER_SYNC();
}

// ---------------------------------------------------------------------------
// Decoder GRU cell: x, h staged in smem
// ---------------------------------------------------------------------------
__device__ __forceinline__ void dec_cell2(const float* sWp,
                                          const float* sx, const float* shv,
                                          float* hw, int u, int lane,
                                          float bi0, float bi1, float bi2,
                                          float bh0, float bh1, float bh2) {
    const float4* xp = (const float4*)sx;
    const float4* hp = (const float4*)shv;
    const float4* w0 = (const float4*)(sWp + 0 * H);
    const float4* w1 = (const float4*)(sWp + 1 * H);
    const float4* w2 = (const float4*)(sWp + 2 * H);
    const float4* w3 = (const float4*)(sWp + 3 * H);
    const float4* w4 = (const float4*)(sWp + 4 * H);
    const float4* w5 = (const float4*)(sWp + 5 * H);
    float a0 = 0.f, a1 = 0.f, a2 = 0.f, a3 = 0.f, a4 = 0.f, a5 = 0.f;
    for (int c = lane; c < 125; c += 32) {
        float4 xv = xp[c];
        float4 hv = hp[c];
        float4 m0 = w0[c], m1 = w1[c], m2 = w2[c];
        float4 m3 = w3[c], m4 = w4[c], m5 = w5[c];
        a0 += m0.x * xv.x + m0.y * xv.y + m0.z * xv.z + m0.w * xv.w;
        a1 += m1.x * xv.x + m1.y * xv.y + m1.z * xv.z + m1.w * xv.w;
        a2 += m2.x * xv.x + m2.y * xv.y + m2.z * xv.z + m2.w * xv.w;
        a3 += m3.x * hv.x + m3.y * hv.y + m3.z * hv.z + m3.w * hv.w;
        a4 += m4.x * hv.x + m4.y * hv.y + m4.z * hv.z + m4.w * hv.w;
        a5 += m5.x * hv.x + m5.y * hv.y + m5.z * hv.z + m5.w * hv.w;
    }
    __syncwarp();
    a0 = wred(a0); a1 = wred(a1); a2 = wred(a2);
    a3 = wred(a3); a4 = wred(a4); a5 = wred(a5);
    if (lane == 0) {
        float r = sigf(a0 + bi0 + a3 + bh0);
        float z = sigf(a1 + bi1 + a4 + bh1);
        float n = tanhf(a2 + bi2 + r * (a5 + bh2));
        stcg(hw + u, (1.f - z) * n + z * shv[u]);
    }
}

// ---------------------------------------------------------------------------
// Persistent greedy decoder — R12 structure, logits loop MLP fix (20-deep)
// ---------------------------------------------------------------------------
__global__ void __cluster_dims__(CLU, 1, 1) __launch_bounds__(DEC_THREADS)
k_decoder(const float* __restrict__ emb,
          const float* __restrict__ dWih, const float* __restrict__ dWhh,
          const float* __restrict__ dbih, const float* __restrict__ dbhh,
          const float* __restrict__ cW, const float* __restrict__ cb,
          const float* __restrict__ oW, const float* __restrict__ ob,
          float* out_tok) {
    extern __shared__ float sW[];
    __shared__ float se[S];
    __shared__ float sred[32];
    __shared__ __align__(16) float sc_c[512];
    __shared__ __align__(16) float sx[512];
    __shared__ __align__(16) float shh[512];
    __shared__ unsigned long long swb[8];
    __shared__ float stile[32][33];

    int tid = threadIdx.x, wid = tid >> 5, lane = tid & 31;
    int grp = blockIdx.x >> 6;
    int cta = blockIdx.x & 63;
    int u = cta * DUPC + wid;
    bool uval = (u < H);
    unsigned long long pol = mkpolicy_el();

    const float* Wih = dWih + (size_t)grp * H3 * H;
    const float* Whh = dWhh + (size_t)grp * H3 * H;
    if (uval) {
#pragma unroll
        for (int r = 0; r < 3; r++) {
            const float* s1 = Wih + (size_t)(u + r * H) * H;
            const float* s2 = Whh + (size_t)(u + r * H) * H;
            float* d1 = sW + (wid * 6 + r) * H;
            float* d2 = sW + (wid * 6 + 3 + r) * H;
            for (int i = lane; i < H; i += 32) {
                d1[i] = __ldg(s1 + i);
                d2[i] = __ldg(s2 + i);
            }
        }
    }
    float bi0 = 0.f, bi1 = 0.f, bi2 = 0.f, bh0 = 0.f, bh1 = 0.f, bh2 = 0.f;
    if (uval) {
        const float* bi = dbih + grp * H3;
        const float* bh = dbhh + grp * H3;
        bi0 = __ldg(bi + u); bi1 = __ldg(bi + H + u); bi2 = __ldg(bi + 2 * H + u);
        bh0 = __ldg(bh + u); bh1 = __ldg(bh + H + u); bh2 = __ldg(bh + 2 * H + u);
    }

    // transpose oW (VxH) -> g_oWT (HxVP), stores primed evict_last
    {
        int tx = tid & 31, ty4 = (tid >> 5) * 4;
        int ntile = ((V + 31) / 32) * 16;
        for (int tile = blockIdx.x; tile < ntile; tile += DEC_CTAS) {
            int tj = tile >> 4, tk = tile & 15;
            __syncthreads();
#pragma unroll
            for (int r = 0; r < 4; r++) {
                int jj = ty4 + r;
                int j = tj * 32 + jj, k = tk * 32 + tx;
                stile[jj][tx] = (j < V && k < H) ? __ldg(oW + (size_t)j * H + k) : 0.f;
            }
            __syncthreads();
#pragma unroll
            for (int r = 0; r < 4; r++) {
                int kk = ty4 + r;
                int k = tk * 32 + kk, j = tj * 32 + tx;
                if (k < H) st_el(&g_oWT[(size_t)k * VP + j], stile[tx][kk], pol);
            }
        }
    }

    unsigned* ctr = &g_ctr[4];
    unsigned round = 0;
    int cur_tok = SOS;
    hbar(ctr, (++round) * NCLUST);

    for (int t = 0; t < MAXL; t++) {
        int p = t & 1;
        if (grp == 0) {
            const float* xg = emb + (size_t)cur_tok * H;
            const float* hg = &g_dh[p][0][0];
            for (int i = tid; i < 512; i += DEC_THREADS) {
                sx[i] = (i < H) ? __ldg(xg + i) : 0.f;
                shh[i] = ldcg(hg + i);
            }
            __syncthreads();
            if (uval)
                dec_cell2(sW + wid * 6 * H, sx, shh, &g_dh[1 - p][0][0],
                          u, lane, bi0, bi1, bi2, bh0, bh1, bh2);
        }
        hbar(ctr, (++round) * NCLUST);
        if (grp == 1) {
            const float* xg = &g_dh[1 - p][0][0];
            const float* hg = &g_dh[p][1][0];
            for (int i = tid; i < 512; i += DEC_THREADS) {
                sx[i] = ldcg(xg + i);
                shh[i] = ldcg(hg + i);
            }
            __syncthreads();
            if (uval)
                dec_cell2(sW + wid * 6 * H, sx, shh, &g_dh[1 - p][1][0],
                          u, lane, bi0, bi1, bi2, bh0, bh1, bh2);
        }
        hbar(ctr, (++round) * NCLUST);
        {
            const float* hg = &g_dh[1 - p][1][0];
            for (int i = tid; i < 512; i += DEC_THREADS) shh[i] = ldcg(hg + i);
            __syncthreads();
            const float4* rp = (const float4*)shh;
            if (wid < 2) {
                int sidx = blockIdx.x * 2 + wid;
                const float4* ep = (const float4*)(g_enc + (size_t)sidx * H);
                float a = 0.f;
                for (int c = lane; c < 125; c += 32) {
                    float4 ev = __ldg(ep + c);
                    float4 rv = rp[c];
                    a += ev.x * rv.x + ev.y * rv.y + ev.z * rv.z + ev.w * rv.w;
                }
                __syncwarp();
                a = wred(a);
                if (lane == 0) stcg(g_scores + sidx, a);
            } else if (wid < 6) {
                int uc = blockIdx.x * 4 + (wid - 2);
                if (uc < H) {
                    const float4* wc = (const float4*)(cW + (size_t)uc * 2 * H);
                    float a = 0.f;
                    for (int c = lane; c < 125; c += 32) {
                        float4 wv = __ldg(wc + c);
                        float4 rv = rp[c];
                        a += wv.x * rv.x + wv.y * rv.y + wv.z * rv.z + wv.w * rv.w;
                    }
                    __syncwarp();
                    a = wred(a);
                    if (lane == 0) stcg(g_wc + uc, a);
                }
            }
        }
        hbar(ctr, (++round) * NCLUST);
        float sc = ldcg(g_scores + tid);
        float m = sc;
#pragma unroll
        for (int o = 16; o; o >>= 1) m = fmaxf(m, __shfl_xor_sync(0xffffffffu, m, o));
        if (lane == 0) sred[wid] = m;
        __syncthreads();
        float bm = sred[0];
#pragma unroll
        for (int i = 1; i < 8; i++) bm = fmaxf(bm, sred[i]);
        float e = expf(sc - bm);
        se[tid] = e;
        float sl = wred(e);
        __syncthreads();
        if (lane == 0) sred[16 + wid] = sl;
        __syncthreads();
        float sumE = sred[16];
#pragma unroll
        for (int i = 1; i < 8; i++) sumE += sred[16 + i];

        if (wid < 4) {
            int uc = blockIdx.x * 4 + wid;
            if (uc < H) {
                const float4* ptp = (const float4*)(g_PT + (size_t)uc * S);
                float a2 = 0.f;
                for (int c = lane; c < 64; c += 32) {
                    float4 pv = __ldg(ptp + c);
                    a2 += pv.x * se[c * 4] + pv.y * se[c * 4 + 1] +
                          pv.z * se[c * 4 + 2] + pv.w * se[c * 4 + 3];
                }
                __syncwarp();
                a2 = wred(a2);
                if (lane == 0) {
                    float a = ldcg(g_wc + uc);
                    stcg(g_c + uc, tanhf(a + a2 / sumE + __ldg(cb + uc)));
                }
            }
        }
        hbar(ctr, (++round) * NCLUST);
        // ---- Stage F: logits — 20-deep load batches (MLP fix) + argmax ----
        for (int i = tid; i < 512; i += DEC_THREADS)
            sc_c[i] = (i < H) ? ldcg(g_c + i) : 0.f;
        __syncthreads();
        int gtid = blockIdx.x * DEC_THREADS + tid;   // 0..32767
        int col = gtid << 1;
        unsigned long long pk = 0ull;
        if (col < V) {
            bool has1 = (col + 1 < V);
            float acc0 = __ldg(ob + col);
            float acc1 = has1 ? __ldg(ob + col + 1) : 0.f;
            const float* wp = g_oWT + col;
#pragma unroll 1
            for (int k0 = 0; k0 < H; k0 += 20) {     // 25 iters, 20 loads in flight
                float2 w[20];
#pragma unroll
                for (int j = 0; j < 20; j++)
                    w[j] = ldg_el2(wp + (size_t)j * VP, pol);
#pragma unroll
                for (int j = 0; j < 20; j++) {
                    float cv = sc_c[k0 + j];
                    acc0 += cv * w[j].x;
                    acc1 += cv * w[j].y;
                }
                wp += 20 * (size_t)VP;
            }
            float* lrow = g_logits + (size_t)t * V;
            stcs(lrow + col, acc0);
            pk = ((unsigned long long)fflip(acc0) << 32) | (unsigned)(~(unsigned)col);
            if (has1) {
                stcs(lrow + col + 1, acc1);
                unsigned long long pk2 =
                    ((unsigned long long)fflip(acc1) << 32) |
                    (unsigned)(~(unsigned)(col + 1));
                if (pk2 > pk) pk = pk2;
            }
        }
#pragma unroll
        for (int o = 16; o; o >>= 1) {
            unsigned long long other = __shfl_xor_sync(0xffffffffu, pk, o);
            if (other > pk) pk = other;
        }
        if (lane == 0) swb[wid] = pk;
        __syncthreads();
        if (tid == 0) {
            unsigned long long b = swb[0];
#pragma unroll
            for (int i = 1; i < 8; i++) if (swb[i] > b) b = swb[i];
            atomicMax(&g_slots[t], b);
        }
        hbar(ctr, (++round) * NCLUST);
        unsigned long long sl64 = ldcg_u64(&g_slots[t]);
        cur_tok = (int)(~(unsigned)(sl64 & 0xFFFFFFFFull));
        if (blockIdx.x == 0 && tid == 0 && out_tok) out_tok[t] = (float)cur_tok;
    }
}

// ---------------------------------------------------------------------------
// Final softmax over stored logits
// ---------------------------------------------------------------------------
__global__ void k_probs(float* __restrict__ out_probs) {
    int t = blockIdx.x;
    int tid = threadIdx.x, wid = tid >> 5, lane = tid & 31;
    __shared__ float sred[32];
    __shared__ float stot;
    const float* lrow = g_logits + (size_t)t * V;
    float mx = unflip((unsigned)(g_slots[t] >> 32));
    float s = 0.f;
    for (int i = tid; i < V; i += blockDim.x) s += expf(lrow[i] - mx);
    s = wred(s);
    if (lane == 0) sred[wid] = s;
    __syncthreads();
    if (tid == 0) {
        float tt = 0.f;
#pragma unroll
        for (int i = 0; i < 32; i++) tt += sred[i];
        stot = tt;
    }
    __syncthreads();
    float inv = 1.f / stot;
    float* orow = out_probs + (size_t)t * V;
    for (int i = tid; i < V; i += blockDim.x) orow[i] = expf(lrow[i] - mx) * inv;
}

// ---------------------------------------------------------------------------
// Host launcher
// ---------------------------------------------------------------------------
extern "C" void kernel_launch(void* const* d_in, const int* in_sizes, int n_in,
                              void* d_out, int out_size) {
    const int* seq = (const int*)d_in[0];
    int i = 1;
    while (i < n_in && in_sizes[i] == 1) i++;
    const float* emb = (const float*)d_in[i++];
    const float* eW[4][4];
    for (int e = 0; e < 4; e++)
        for (int w = 0; w < 4; w++) eW[e][w] = (const float*)d_in[i++];
    const float* dWih = (const float*)d_in[i++];
    const float* dWhh = (const float*)d_in[i++];
    const float* dbih = (const float*)d_in[i++];
    const float* dbhh = (const float*)d_in[i++];
    const float* cW   = (const float*)d_in[i++];
    const float* cb   = (const float*)d_in[i++];
    const float* oW   = (const float*)d_in[i++];
    const float* ob   = (const float*)d_in[i++];

    float* out = (float*)d_out;
    int has_tok = (out_size >= MAXL * V + MAXL);
    float* out_tok = has_tok ? out : nullptr;
    float* out_probs = out + (has_tok ? MAXL : 0);

    int scan_smem = (SC_UPC * 3 * H + 1024) * 4;   // 196096 bytes
    cudaFuncSetAttribute(k_scan, cudaFuncAttributeMaxDynamicSharedMemorySize,
                         scan_smem);
    cudaFuncSetAttribute(k_scan, cudaFuncAttributeNonPortableClusterSizeAllowed, 1);
    cudaFuncSetAttribute(k_decoder, cudaFuncAttributeMaxDynamicSharedMemorySize,
                         DUPC * 6 * H * 4);

    void *p_gxf, *p_gxb, *p_x1;
    cudaGetSymbolAddress(&p_gxf, g_gxf);
    cudaGetSymbolAddress(&p_gxb, g_gxb);
    cudaGetSymbolAddress(&p_x1, g_x1);

    // cluster-16 launch config for the scans
    cudaLaunchConfig_t scfg = {};
    scfg.gridDim = dim3(2 * SC_CPD, 1, 1);
    scfg.blockDim = dim3(SC_THREADS, 1, 1);
    scfg.dynamicSmemBytes = scan_smem;
    scfg.stream = 0;
    cudaLaunchAttribute sattr[1];
    sattr[0].id = cudaLaunchAttributeClusterDimension;
    sattr[0].val.clusterDim.x = SC_CPD;
    sattr[0].val.clusterDim.y = 1;
    sattr[0].val.clusterDim.z = 1;
    scfg.attrs = sattr;
    scfg.numAttrs = 1;

    dim3 tb(32, 8);
    // #1 init + layer-0 gx (indirect A via seq), both directions
    k_pre<<<dim3(47, 8, 2), tb>>>(seq, emb, eW[0][0], eW[1][0],
                                  eW[0][2], eW[1][2],
                                  (float*)p_gxf, (float*)p_gxb);
    // #2 scan layer 0 (cluster 16)
    cudaLaunchKernelEx(&scfg, k_scan, 0, eW[0][1], eW[1][1],
                       eW[0][3], eW[1][3], cW);
    // #3 layer-1 gx (K=1000), both directions
    k_gemm2<<<dim3((H3 + 31) / 32, (S + 31) / 32, 2), tb>>>(
        (const float*)p_x1, 2 * H, eW[2][0], eW[3][0], 2 * H, eW[2][2], eW[3][2],
        (float*)p_gxf, (float*)p_gxb, H3, S, H3, 2 * H);
    // #4 scan layer 1 + epilogue (cluster 16)
    cudaLaunchKernelEx(&scfg, k_scan, 1, eW[2][1], eW[3][1],
                       eW[2][3], eW[3][3], cW);
    // #5 decoder
    k_decoder<<<DEC_CTAS, DEC_THREADS, DUPC * 6 * H * 4>>>(
        emb, dWih, dWhh, dbih, dbhh, cW, cb, oW, ob, out_tok);
    // #6 probs
    k_probs<<<MAXL, 1024>>>(out_probs);
}